// round 8
// baseline (speedup 1.0000x reference)
#include <cuda_runtime.h>
#include <cuda_fp16.h>
#include <cstdint>
#include <math.h>

// Problem constants
#define BZ     1024
#define DNUM   200
#define FEATD  256
#define HIDD   256
#define VOCAB  100000
#define MTOT   (BZ*DNUM)        // 204800 tokens
#define TILE_M 64
#define NTILES (MTOT/TILE_M)    // 3200
#define PTILES ((VOCAB + TILE_M - 1)/TILE_M)   // 1563

// ---------------- device scratch (no allocations allowed) ----------------
__device__ __half g_B[2*8*8192];               // fragment-major fp16 weights
__device__ __half g_P[(size_t)(PTILES*TILE_M)*256];  // ebd @ W_id, fp16
__device__ __half g_feat16[(size_t)MTOT*256];  // fp16 copy of feat (written by GEMM)
__device__ float  g_logits[MTOT];

// ---------------- helpers ----------------
__device__ __forceinline__ uint32_t smem_u32(const void* p) {
    uint32_t a;
    asm("{ .reg .u64 t; cvta.to.shared.u64 t, %1; cvt.u32.u64 %0, t; }" : "=r"(a) : "l"(p));
    return a;
}

#define CP_ASYNC16(dst_u32, src_ptr) \
    asm volatile("cp.async.cg.shared.global [%0], [%1], 16;" :: "r"(dst_u32), "l"(src_ptr) : "memory")
#define CP_COMMIT()  asm volatile("cp.async.commit_group;" ::: "memory")
#define CP_WAIT0()   asm volatile("cp.async.wait_group 0;" ::: "memory")

#define MMA16(d, a, b) \
    asm volatile("mma.sync.aligned.m16n8k16.row.col.f32.f16.f16.f32 " \
        "{%0,%1,%2,%3},{%4,%5,%6,%7},{%8,%9},{%0,%1,%2,%3};" \
        : "+f"((d)[0]), "+f"((d)[1]), "+f"((d)[2]), "+f"((d)[3]) \
        : "r"((a).x), "r"((a).y), "r"((a).z), "r"((a).w), "r"((b).x), "r"((b).y))

// smem stage: [A fragmajor 4KB][B fragmajor 16KB] x 2 buffers (+ P region in token kernel)
#define ASTAGE 4096
#define BSTAGE 16384
#define STAGE  (ASTAGE + BSTAGE)
#define POFF   (2*STAGE)                 // 40960
#define PPITCHB 528                      // 33 uint4 per row (conflict-free)
#define SMEM_PRE  (2*STAGE)              // 40960
#define SMEM_TOK  (2*STAGE + TILE_M*PPITCHB)   // 74752

// ============================================================
// Kernel 0: convert weights to fp16 in mma-fragment order.
// ============================================================
__global__ void prep_w_kernel(const float* __restrict__ Wrv, const float* __restrict__ Wid) {
    int idx = blockIdx.x * blockDim.x + threadIdx.x;
    if (idx >= 2*65536) return;
    int src = idx >> 16;
    int r   = idx & 65535;
    int k   = r >> 8;
    int n   = r & 255;
    const float* W = src ? Wid : Wrv;
    float v = W[k*256 + n];
    int chunk = k >> 5, k5 = k & 31;
    int s = k5 >> 4, kk = k5 & 15;
    int tg = (kk >> 1) & 3, kh = kk >> 3, kbit = kk & 1;
    int nf = n >> 3, g = n & 7, lane = g*4 + tg;
    g_B[(src*8 + chunk)*8192 + ((s*32 + nf)*32 + lane)*4 + kh*2 + kbit] = __float2half(v);
}

// ---------------- shared GEMM machinery (macros) ----------------
#define DECL_STS_OFF(a_sts_off)                                               \
    int a_sts_off[2][2];                                                      \
    _Pragma("unroll")                                                         \
    for (int it = 0; it < 2; it++) {                                          \
        int idx = threadIdx.x + it*256;                                       \
        int row = idx >> 3, q = idx & 7;                                      \
        int s = q >> 2, kh = (q >> 1) & 1;                                    \
        int mf = row >> 4, rr = row & 15, g2 = rr & 7, ab = rr >> 3;          \
        int comp = kh*2 + ab;                                                 \
        int lane0 = g2*4 + 2*(q & 1);                                         \
        a_sts_off[it][0] = ((s*4 + mf)*32 + lane0)*4 + comp;                  \
        a_sts_off[it][1] = ((s*4 + mf)*32 + lane0 + 1)*4 + comp;              \
    }

#define STS_A(buf_) do {                                                      \
    uint32_t* As_ = (uint32_t*)(dsm + (buf_)*STAGE);                          \
    _Pragma("unroll")                                                         \
    for (int it = 0; it < 2; it++) {                                          \
        __half2 p0 = __floats2half2_rn(areg[it].x, areg[it].y);               \
        __half2 p1 = __floats2half2_rn(areg[it].z, areg[it].w);               \
        As_[a_sts_off[it][0]] = *(uint32_t*)&p0;                              \
        As_[a_sts_off[it][1]] = *(uint32_t*)&p1;                              \
    }                                                                         \
} while(0)

// token variant: also streams the fp16 conversion to g_feat16 (coalesced)
#define STS_AF(buf_, kc_) do {                                                \
    uint32_t* As_ = (uint32_t*)(dsm + (buf_)*STAGE);                          \
    _Pragma("unroll")                                                         \
    for (int it = 0; it < 2; it++) {                                          \
        __half2 p0 = __floats2half2_rn(areg[it].x, areg[it].y);               \
        __half2 p1 = __floats2half2_rn(areg[it].z, areg[it].w);               \
        As_[a_sts_off[it][0]] = *(uint32_t*)&p0;                              \
        As_[a_sts_off[it][1]] = *(uint32_t*)&p1;                              \
        int idx = tid + it*256;                                               \
        int row = idx >> 3, q = idx & 7;                                      \
        uint2 v; v.x = *(uint32_t*)&p0; v.y = *(uint32_t*)&p1;                \
        *(uint2*)(g_feat16 + ((size_t)(tile*TILE_M + row)*256                 \
                              + (kc_)*32 + q*4)) = v;                         \
    }                                                                         \
} while(0)

// cp.async of one B chunk WITHOUT commit (caller commits the group)
#define CP_B_NC(bsrc_, kc_, buf_) do {                                        \
    const char* gsrc = (const char*)(g_B + ((bsrc_)*8 + (kc_))*8192);         \
    uint32_t dstb = sbase + (buf_)*STAGE + ASTAGE;                            \
    _Pragma("unroll")                                                         \
    for (int it = 0; it < 4; it++) {                                          \
        int off = (tid + it*256)*16;                                          \
        CP_ASYNC16(dstb + off, gsrc + off);                                   \
    }                                                                         \
} while(0)

#define COMPUTE_CHUNK(buf_) do {                                              \
    const uint4* As_ = (const uint4*)(dsm + (buf_)*STAGE);                    \
    const uint2* Bs_ = (const uint2*)(dsm + (buf_)*STAGE + ASTAGE);           \
    _Pragma("unroll")                                                         \
    for (int s = 0; s < 2; s++) {                                             \
        uint4 af[2];                                                          \
        _Pragma("unroll")                                                     \
        for (int i = 0; i < 2; i++)                                           \
            af[i] = As_[(s*4 + warp_m*2 + i)*32 + lane];                      \
        uint2 bf[8];                                                          \
        _Pragma("unroll")                                                     \
        for (int j = 0; j < 8; j++)                                           \
            bf[j] = Bs_[(s*32 + warp_n*8 + j)*32 + lane];                     \
        _Pragma("unroll")                                                     \
        for (int i = 0; i < 2; i++)                                           \
            _Pragma("unroll")                                                 \
            for (int j = 0; j < 8; j++)                                       \
                MMA16(acc[i][j], af[i], bf[j]);                               \
    }                                                                         \
} while(0)

// ============================================================
// Kernel A: precompute P = ebd @ W_id (fp16), coalesced store via smem restage.
// ============================================================
__global__ __launch_bounds__(256, 2)
void precompute_p_kernel(const float4* __restrict__ ebd4)
{
    extern __shared__ char dsm[];
    const int tid  = threadIdx.x;
    const int lane = tid & 31;
    const int wid  = tid >> 5;
    const int warp_m = wid >> 2;
    const int warp_n = wid & 3;
    const int tile = blockIdx.x;
    const uint32_t sbase = smem_u32(dsm);

    DECL_STS_OFF(a_sts_off);
    float4 areg[2];

    #define LDG_E(kc_) do {                                                   \
        _Pragma("unroll")                                                     \
        for (int it = 0; it < 2; it++) {                                      \
            int idx = tid + it*256;                                           \
            int row = idx >> 3, q = idx & 7;                                  \
            int grow = tile*TILE_M + row;                                     \
            areg[it] = (grow < VOCAB) ? ebd4[(size_t)grow*64 + (kc_)*8 + q]   \
                                      : make_float4(0.f,0.f,0.f,0.f);         \
        }                                                                     \
    } while(0)

    float acc[2][8][4];
    #pragma unroll
    for (int i = 0; i < 2; i++)
        #pragma unroll
        for (int j = 0; j < 8; j++)
            #pragma unroll
            for (int t = 0; t < 4; t++) acc[i][j][t] = 0.f;

    LDG_E(0);
    CP_B_NC(1, 0, 0); CP_COMMIT();
    STS_A(0);
    CP_WAIT0();
    __syncthreads();

    for (int c = 0; c < 8; c++) {
        int buf = c & 1;
        if (c < 7) { LDG_E(c+1); CP_B_NC(1, c+1, buf^1); CP_COMMIT(); }
        COMPUTE_CHUNK(buf);
        if (c < 7) { STS_A(buf^1); CP_WAIT0(); }
        __syncthreads();
    }

    // restage accumulators (fp16) into smem with conflict-free pitch
    {
        uint32_t* Pst = (uint32_t*)dsm;   // row pitch 132 words
        const int g  = lane >> 2;
        const int tg = lane & 3;
        #pragma unroll
        for (int i = 0; i < 2; i++) {
            int r0 = warp_m*32 + i*16 + g;
            int r1 = r0 + 8;
            #pragma unroll
            for (int j = 0; j < 8; j++) {
                int cw = (warp_n*64 + j*8 + tg*2) >> 1;
                __half2 v0 = __floats2half2_rn(acc[i][j][0], acc[i][j][1]);
                __half2 v1 = __floats2half2_rn(acc[i][j][2], acc[i][j][3]);
                Pst[r0*132 + cw] = *(uint32_t*)&v0;
                Pst[r1*132 + cw] = *(uint32_t*)&v1;
            }
        }
    }
    __syncthreads();

    // coalesced store: 512B per row; row 0 forced to zero (padding_idx)
    {
        const uint4* Pst4 = (const uint4*)dsm;
        #pragma unroll
        for (int it = 0; it < 8; it++) {
            int s = tid + it*256;          // 0..2047
            int row = s >> 5, q = s & 31;
            int grow = tile*TILE_M + row;
            uint4 v = Pst4[row*33 + q];
            if (grow == 0) v = make_uint4(0u,0u,0u,0u);
            ((uint4*)g_P)[(size_t)grow*32 + q] = v;
        }
    }
}

// ============================================================
// Kernel B: token GEMM feat @ W_rv (K=256); P[id] gathered via cp.async,
// one 256-uint4 slice per chunk riding in the B-chunk's commit group.
// ============================================================
__global__ __launch_bounds__(256, 2)
void gemm_logits_kernel(const float4* __restrict__ feat4,
                        const int*    __restrict__ other_id,
                        const float*  __restrict__ b1,
                        const float*  __restrict__ hvec,
                        const float*  __restrict__ b2p)
{
    extern __shared__ char dsm[];
    __shared__ int   ids[TILE_M];
    __shared__ float b1s[HIDD];
    __shared__ float hs[HIDD];
    __shared__ float part[TILE_M];

    const int tid  = threadIdx.x;
    const int lane = tid & 31;
    const int wid  = tid >> 5;
    const int warp_m = wid >> 2;
    const int warp_n = wid & 3;
    const int tile = blockIdx.x;
    const uint32_t sbase = smem_u32(dsm);

    if (tid < TILE_M) { ids[tid] = other_id[tile*TILE_M + tid]; part[tid] = 0.f; }
    b1s[tid] = b1[tid];
    hs[tid]  = hvec[tid];
    __syncthreads();                 // ids visible before any P slice

    DECL_STS_OFF(a_sts_off);
    float4 areg[2];

    #define LDG_F(kc_) do {                                                   \
        _Pragma("unroll")                                                     \
        for (int it = 0; it < 2; it++) {                                      \
            int idx = tid + it*256;                                           \
            int row = idx >> 3, q = idx & 7;                                  \
            areg[it] = feat4[(size_t)(tile*TILE_M + row)*64 + (kc_)*8 + q];   \
        }                                                                     \
    } while(0)

    #define CP_P_SLICE(sl_) do {                                              \
        int s_ = (sl_)*256 + tid;                                             \
        int row_ = s_ >> 5, q_ = s_ & 31;                                     \
        int id_ = ids[row_];                                                  \
        CP_ASYNC16(sbase + POFF + row_*PPITCHB + q_*16,                       \
                   (const char*)(g_P + (size_t)id_*256) + q_*16);             \
    } while(0)

    float acc[2][8][4];
    #pragma unroll
    for (int i = 0; i < 2; i++)
        #pragma unroll
        for (int j = 0; j < 8; j++)
            #pragma unroll
            for (int t = 0; t < 4; t++) acc[i][j][t] = 0.f;

    LDG_F(0);
    CP_B_NC(0, 0, 0); CP_P_SLICE(0); CP_COMMIT();
    STS_AF(0, 0);
    CP_WAIT0();
    __syncthreads();

    for (int c = 0; c < 8; c++) {
        int buf = c & 1;
        if (c < 7) {
            LDG_F(c+1);
            CP_B_NC(0, c+1, buf^1); CP_P_SLICE(c+1); CP_COMMIT();
        }
        COMPUTE_CHUNK(buf);
        if (c < 7) { STS_AF(buf^1, c+1); CP_WAIT0(); }
        __syncthreads();
    }

    // ---- epilogue: logit_row = sum_col relu(acc + P + b1[col]) * h[col] ----
    {
        const __half2* Ps = (const __half2*)(dsm + POFF);   // pitch 132 half2
        const int g   = lane >> 2;
        const int tg  = lane & 3;
        #pragma unroll
        for (int i = 0; i < 2; i++) {
            float p0 = 0.f, p1 = 0.f;
            int r0 = warp_m*32 + i*16 + g;
            #pragma unroll
            for (int j = 0; j < 8; j++) {
                int c0 = warp_n*64 + j*8 + tg*2;
                int c1 = c0 + 1;
                float2 pa = __half22float2(Ps[r0*132 + (c0>>1)]);
                float2 pb = __half22float2(Ps[(r0+8)*132 + (c0>>1)]);
                float h0 = hs[c0], h1 = hs[c1];
                float bb0 = b1s[c0], bb1 = b1s[c1];
                p0 += fmaxf(acc[i][j][0] + pa.x + bb0, 0.f) * h0
                    + fmaxf(acc[i][j][1] + pa.y + bb1, 0.f) * h1;
                p1 += fmaxf(acc[i][j][2] + pb.x + bb0, 0.f) * h0
                    + fmaxf(acc[i][j][3] + pb.y + bb1, 0.f) * h1;
            }
            p0 += __shfl_xor_sync(0xffffffffu, p0, 1);
            p0 += __shfl_xor_sync(0xffffffffu, p0, 2);
            p1 += __shfl_xor_sync(0xffffffffu, p1, 1);
            p1 += __shfl_xor_sync(0xffffffffu, p1, 2);
            if (tg == 0) {
                atomicAdd(&part[r0],     p0);
                atomicAdd(&part[r0 + 8], p1);
            }
        }
    }
    __syncthreads();
    if (tid < TILE_M) g_logits[tile*TILE_M + tid] = part[tid] + b2p[0];
}

// ============================================================
// Kernel C: softmax + weighted sum, feature-split: grid (BZ, 2).
// CTA (b, half) reduces 128 features. Warp w handles rows d = w+8t;
// lane loads uint2 (4 halves) at the half's 256B row segment.
// ============================================================
#define SACC_PITCH 132
__global__ __launch_bounds__(256)
void softmax_out_kernel(float* __restrict__ out, int write_att)
{
    __shared__ float s[DNUM];
    __shared__ float wsum[8];
    __shared__ float sinv;
    __shared__ float sacc[8*SACC_PITCH];
    int b = blockIdx.x, half = blockIdx.y, tid = threadIdx.x;
    int w = tid >> 5, lane = tid & 31;

    float e = 0.f;
    if (tid < DNUM) { e = expf(g_logits[b*DNUM + tid]); s[tid] = e; }
    float v = e;
    #pragma unroll
    for (int o = 16; o > 0; o >>= 1) v += __shfl_down_sync(0xffffffffu, v, o);
    if (lane == 0) wsum[w] = v;
    __syncthreads();
    if (tid == 0) {
        float S = 0.f;
        #pragma unroll
        for (int i = 0; i < 8; i++) S += wsum[i];
        sinv = 1.f / (S + 1e-8f);
    }
    __syncthreads();
    float inv = sinv;
    if (tid < DNUM) {
        float sc = s[tid] * inv;
        s[tid] = sc;
        if (write_att && half == 0) out[BZ*FEATD + b*DNUM + tid] = sc;
    }
    __syncthreads();

    // weighted sum over 128 features: lane handles features half*128 + lane*4..+3
    const uint2* fb = (const uint2*)(g_feat16 + (size_t)b * DNUM * 256);
    float a0=0.f,a1=0.f,a2=0.f,a3=0.f;
    #pragma unroll 5
    for (int t = 0; t < 25; t++) {
        int d = w + t*8;
        float sd = s[d];
        uint2 r = fb[d*64 + half*32 + lane];
        float2 f0 = __half22float2(*(__half2*)&r.x);
        float2 f1 = __half22float2(*(__half2*)&r.y);
        a0 += sd*f0.x; a1 += sd*f0.y; a2 += sd*f1.x; a3 += sd*f1.y;
    }
    {
        float* sa = sacc + w*SACC_PITCH + lane*4;
        sa[0]=a0; sa[1]=a1; sa[2]=a2; sa[3]=a3;
    }
    __syncthreads();
    if (tid < 128) {
        float r = 0.f;
        #pragma unroll
        for (int ww = 0; ww < 8; ww++) r += sacc[ww*SACC_PITCH + tid];
        out[b*FEATD + half*128 + tid] = r;
    }
}

// ============================================================
extern "C" void kernel_launch(void* const* d_in, const int* in_sizes, int n_in,
                              void* d_out, int out_size)
{
    const float* feat     = (const float*)d_in[0];
    const int*   other_id = (const int*)  d_in[1];
    const float* Wrv      = (const float*)d_in[2];
    const float* Wid      = (const float*)d_in[3];
    const float* hvec     = (const float*)d_in[4];
    const float* b1       = (const float*)d_in[5];
    const float* b2       = (const float*)d_in[6];
    const float* ebd      = (const float*)d_in[7];
    float* out = (float*)d_out;

    cudaFuncSetAttribute(precompute_p_kernel,
                         cudaFuncAttributeMaxDynamicSharedMemorySize, SMEM_PRE);
    cudaFuncSetAttribute(gemm_logits_kernel,
                         cudaFuncAttributeMaxDynamicSharedMemorySize, SMEM_TOK);

    prep_w_kernel<<<512, 256>>>(Wrv, Wid);
    precompute_p_kernel<<<PTILES, 256, SMEM_PRE>>>((const float4*)ebd);
    gemm_logits_kernel<<<NTILES, 256, SMEM_TOK>>>(
        (const float4*)feat, other_id, b1, hvec, b2);

    int write_att = (out_size >= BZ*FEATD + BZ*DNUM) ? 1 : 0;
    dim3 sgrid(BZ, 2);
    softmax_out_kernel<<<sgrid, 256>>>(out, write_att);
}

// round 11
// speedup vs baseline: 1.0458x; 1.0458x over previous
#include <cuda_runtime.h>
#include <cuda_fp16.h>
#include <cstdint>
#include <math.h>

// Problem constants
#define BZ     1024
#define DNUM   200
#define FEATD  256
#define HIDD   256
#define VOCAB  100000
#define MTOT   (BZ*DNUM)        // 204800 tokens
#define TILE_M 64
#define NTILES (MTOT/TILE_M)    // 3200
#define PTILES ((VOCAB + TILE_M - 1)/TILE_M)   // 1563

// ---------------- device scratch (no allocations allowed) ----------------
__device__ __half g_B[2*8*8192];               // fragment-major fp16 weights
__device__ __half g_P[(size_t)(PTILES*TILE_M)*256];  // ebd @ W_id, fp16
__device__ __half g_feat16[(size_t)MTOT*256];  // fp16 copy of feat (written by GEMM)
__device__ float  g_logits[MTOT];

// ---------------- helpers ----------------
__device__ __forceinline__ uint32_t smem_u32(const void* p) {
    uint32_t a;
    asm("{ .reg .u64 t; cvta.to.shared.u64 t, %1; cvt.u32.u64 %0, t; }" : "=r"(a) : "l"(p));
    return a;
}

#define CP_ASYNC16(dst_u32, src_ptr) \
    asm volatile("cp.async.cg.shared.global [%0], [%1], 16;" :: "r"(dst_u32), "l"(src_ptr) : "memory")
#define CP_COMMIT()  asm volatile("cp.async.commit_group;" ::: "memory")
#define CP_WAIT0()   asm volatile("cp.async.wait_group 0;" ::: "memory")

#define MMA16(d, a, b) \
    asm volatile("mma.sync.aligned.m16n8k16.row.col.f32.f16.f16.f32 " \
        "{%0,%1,%2,%3},{%4,%5,%6,%7},{%8,%9},{%0,%1,%2,%3};" \
        : "+f"((d)[0]), "+f"((d)[1]), "+f"((d)[2]), "+f"((d)[3]) \
        : "r"((a).x), "r"((a).y), "r"((a).z), "r"((a).w), "r"((b).x), "r"((b).y))

// smem stage: [A fragmajor 4KB][B fragmajor 16KB] x 2 buffers (+ P region in token kernel)
#define ASTAGE 4096
#define BSTAGE 16384
#define STAGE  (ASTAGE + BSTAGE)
#define POFF   (2*STAGE)                 // 40960
#define PPITCHB 528                      // 33 uint4 per row (conflict-free)
#define SMEM_PRE  (2*STAGE)              // 40960
#define SMEM_TOK  (2*STAGE + TILE_M*PPITCHB)   // 74752

// ============================================================
// Kernel 0: convert weights to fp16 in mma-fragment order.
// ============================================================
__global__ void prep_w_kernel(const float* __restrict__ Wrv, const float* __restrict__ Wid) {
    int idx = blockIdx.x * blockDim.x + threadIdx.x;
    if (idx >= 2*65536) return;
    int src = idx >> 16;
    int r   = idx & 65535;
    int k   = r >> 8;
    int n   = r & 255;
    const float* W = src ? Wid : Wrv;
    float v = W[k*256 + n];
    int chunk = k >> 5, k5 = k & 31;
    int s = k5 >> 4, kk = k5 & 15;
    int tg = (kk >> 1) & 3, kh = kk >> 3, kbit = kk & 1;
    int nf = n >> 3, g = n & 7, lane = g*4 + tg;
    g_B[(src*8 + chunk)*8192 + ((s*32 + nf)*32 + lane)*4 + kh*2 + kbit] = __float2half(v);
}

// ---------------- shared GEMM machinery (macros) ----------------
#define DECL_STS_OFF(a_sts_off)                                               \
    int a_sts_off[2][2];                                                      \
    _Pragma("unroll")                                                         \
    for (int it = 0; it < 2; it++) {                                          \
        int idx = threadIdx.x + it*256;                                       \
        int row = idx >> 3, q = idx & 7;                                      \
        int s = q >> 2, kh = (q >> 1) & 1;                                    \
        int mf = row >> 4, rr = row & 15, g2 = rr & 7, ab = rr >> 3;          \
        int comp = kh*2 + ab;                                                 \
        int lane0 = g2*4 + 2*(q & 1);                                         \
        a_sts_off[it][0] = ((s*4 + mf)*32 + lane0)*4 + comp;                  \
        a_sts_off[it][1] = ((s*4 + mf)*32 + lane0 + 1)*4 + comp;              \
    }

#define STS_A(buf_) do {                                                      \
    uint32_t* As_ = (uint32_t*)(dsm + (buf_)*STAGE);                          \
    _Pragma("unroll")                                                         \
    for (int it = 0; it < 2; it++) {                                          \
        __half2 p0 = __floats2half2_rn(areg[it].x, areg[it].y);               \
        __half2 p1 = __floats2half2_rn(areg[it].z, areg[it].w);               \
        As_[a_sts_off[it][0]] = *(uint32_t*)&p0;                              \
        As_[a_sts_off[it][1]] = *(uint32_t*)&p1;                              \
    }                                                                         \
} while(0)

// token variant: also streams the fp16 conversion to g_feat16 (coalesced)
#define STS_AF(buf_, kc_) do {                                                \
    uint32_t* As_ = (uint32_t*)(dsm + (buf_)*STAGE);                          \
    _Pragma("unroll")                                                         \
    for (int it = 0; it < 2; it++) {                                          \
        __half2 p0 = __floats2half2_rn(areg[it].x, areg[it].y);               \
        __half2 p1 = __floats2half2_rn(areg[it].z, areg[it].w);               \
        As_[a_sts_off[it][0]] = *(uint32_t*)&p0;                              \
        As_[a_sts_off[it][1]] = *(uint32_t*)&p1;                              \
        int idx = tid + it*256;                                               \
        int row = idx >> 3, q = idx & 7;                                      \
        uint2 v; v.x = *(uint32_t*)&p0; v.y = *(uint32_t*)&p1;                \
        *(uint2*)(g_feat16 + ((size_t)(tile*TILE_M + row)*256                 \
                              + (kc_)*32 + q*4)) = v;                         \
    }                                                                         \
} while(0)

// cp.async of one B chunk WITHOUT commit (caller commits the group)
#define CP_B_NC(bsrc_, kc_, buf_) do {                                        \
    const char* gsrc = (const char*)(g_B + ((bsrc_)*8 + (kc_))*8192);         \
    uint32_t dstb = sbase + (buf_)*STAGE + ASTAGE;                            \
    _Pragma("unroll")                                                         \
    for (int it = 0; it < 4; it++) {                                          \
        int off = (tid + it*256)*16;                                          \
        CP_ASYNC16(dstb + off, gsrc + off);                                   \
    }                                                                         \
} while(0)

#define COMPUTE_CHUNK(buf_) do {                                              \
    const uint4* As_ = (const uint4*)(dsm + (buf_)*STAGE);                    \
    const uint2* Bs_ = (const uint2*)(dsm + (buf_)*STAGE + ASTAGE);           \
    _Pragma("unroll")                                                         \
    for (int s = 0; s < 2; s++) {                                             \
        uint4 af[2];                                                          \
        _Pragma("unroll")                                                     \
        for (int i = 0; i < 2; i++)                                           \
            af[i] = As_[(s*4 + warp_m*2 + i)*32 + lane];                      \
        uint2 bf[8];                                                          \
        _Pragma("unroll")                                                     \
        for (int j = 0; j < 8; j++)                                           \
            bf[j] = Bs_[(s*32 + warp_n*8 + j)*32 + lane];                     \
        _Pragma("unroll")                                                     \
        for (int i = 0; i < 2; i++)                                           \
            _Pragma("unroll")                                                 \
            for (int j = 0; j < 8; j++)                                       \
                MMA16(acc[i][j], af[i], bf[j]);                               \
    }                                                                         \
} while(0)

// ============================================================
// Kernel A: precompute P = ebd @ W_id (fp16), coalesced store via smem restage.
// ============================================================
__global__ __launch_bounds__(256, 2)
void precompute_p_kernel(const float4* __restrict__ ebd4)
{
    extern __shared__ char dsm[];
    const int tid  = threadIdx.x;
    const int lane = tid & 31;
    const int wid  = tid >> 5;
    const int warp_m = wid >> 2;
    const int warp_n = wid & 3;
    const int tile = blockIdx.x;
    const uint32_t sbase = smem_u32(dsm);

    DECL_STS_OFF(a_sts_off);
    float4 areg[2];

    #define LDG_E(kc_) do {                                                   \
        _Pragma("unroll")                                                     \
        for (int it = 0; it < 2; it++) {                                      \
            int idx = tid + it*256;                                           \
            int row = idx >> 3, q = idx & 7;                                  \
            int grow = tile*TILE_M + row;                                     \
            areg[it] = (grow < VOCAB) ? ebd4[(size_t)grow*64 + (kc_)*8 + q]   \
                                      : make_float4(0.f,0.f,0.f,0.f);         \
        }                                                                     \
    } while(0)

    float acc[2][8][4];
    #pragma unroll
    for (int i = 0; i < 2; i++)
        #pragma unroll
        for (int j = 0; j < 8; j++)
            #pragma unroll
            for (int t = 0; t < 4; t++) acc[i][j][t] = 0.f;

    LDG_E(0);
    CP_B_NC(1, 0, 0); CP_COMMIT();
    STS_A(0);
    CP_WAIT0();
    __syncthreads();

    for (int c = 0; c < 8; c++) {
        int buf = c & 1;
        if (c < 7) { LDG_E(c+1); CP_B_NC(1, c+1, buf^1); CP_COMMIT(); }
        COMPUTE_CHUNK(buf);
        if (c < 7) { STS_A(buf^1); CP_WAIT0(); }
        __syncthreads();
    }

    // restage accumulators (fp16) into smem with conflict-free pitch
    {
        uint32_t* Pst = (uint32_t*)dsm;   // row pitch 132 words
        const int g  = lane >> 2;
        const int tg = lane & 3;
        #pragma unroll
        for (int i = 0; i < 2; i++) {
            int r0 = warp_m*32 + i*16 + g;
            int r1 = r0 + 8;
            #pragma unroll
            for (int j = 0; j < 8; j++) {
                int cw = (warp_n*64 + j*8 + tg*2) >> 1;
                __half2 v0 = __floats2half2_rn(acc[i][j][0], acc[i][j][1]);
                __half2 v1 = __floats2half2_rn(acc[i][j][2], acc[i][j][3]);
                Pst[r0*132 + cw] = *(uint32_t*)&v0;
                Pst[r1*132 + cw] = *(uint32_t*)&v1;
            }
        }
    }
    __syncthreads();

    // coalesced store: 512B per row; row 0 forced to zero (padding_idx)
    {
        const uint4* Pst4 = (const uint4*)dsm;
        #pragma unroll
        for (int it = 0; it < 8; it++) {
            int s = tid + it*256;          // 0..2047
            int row = s >> 5, q = s & 31;
            int grow = tile*TILE_M + row;
            uint4 v = Pst4[row*33 + q];
            if (grow == 0) v = make_uint4(0u,0u,0u,0u);
            ((uint4*)g_P)[(size_t)grow*32 + q] = v;
        }
    }
}

// ============================================================
// Kernel B: token GEMM feat @ W_rv (K=256); P[id] gathered via cp.async,
// one 256-uint4 slice per chunk riding in the B-chunk's commit group.
// ============================================================
__global__ __launch_bounds__(256, 2)
void gemm_logits_kernel(const float4* __restrict__ feat4,
                        const int*    __restrict__ other_id,
                        const float*  __restrict__ b1,
                        const float*  __restrict__ hvec,
                        const float*  __restrict__ b2p)
{
    extern __shared__ char dsm[];
    __shared__ int   ids[TILE_M];
    __shared__ float b1s[HIDD];
    __shared__ float hs[HIDD];
    __shared__ float part[TILE_M];

    const int tid  = threadIdx.x;
    const int lane = tid & 31;
    const int wid  = tid >> 5;
    const int warp_m = wid >> 2;
    const int warp_n = wid & 3;
    const int tile = blockIdx.x;
    const uint32_t sbase = smem_u32(dsm);

    if (tid < TILE_M) { ids[tid] = other_id[tile*TILE_M + tid]; part[tid] = 0.f; }
    b1s[tid] = b1[tid];
    hs[tid]  = hvec[tid];
    __syncthreads();                 // ids visible before any P slice

    DECL_STS_OFF(a_sts_off);
    float4 areg[2];

    #define LDG_F(kc_) do {                                                   \
        _Pragma("unroll")                                                     \
        for (int it = 0; it < 2; it++) {                                      \
            int idx = tid + it*256;                                           \
            int row = idx >> 3, q = idx & 7;                                  \
            areg[it] = feat4[(size_t)(tile*TILE_M + row)*64 + (kc_)*8 + q];   \
        }                                                                     \
    } while(0)

    #define CP_P_SLICE(sl_) do {                                              \
        int s_ = (sl_)*256 + tid;                                             \
        int row_ = s_ >> 5, q_ = s_ & 31;                                     \
        int id_ = ids[row_];                                                  \
        CP_ASYNC16(sbase + POFF + row_*PPITCHB + q_*16,                       \
                   (const char*)(g_P + (size_t)id_*256) + q_*16);             \
    } while(0)

    float acc[2][8][4];
    #pragma unroll
    for (int i = 0; i < 2; i++)
        #pragma unroll
        for (int j = 0; j < 8; j++)
            #pragma unroll
            for (int t = 0; t < 4; t++) acc[i][j][t] = 0.f;

    LDG_F(0);
    CP_B_NC(0, 0, 0); CP_P_SLICE(0); CP_COMMIT();
    STS_AF(0, 0);
    CP_WAIT0();
    __syncthreads();

    for (int c = 0; c < 8; c++) {
        int buf = c & 1;
        if (c < 7) {
            LDG_F(c+1);
            CP_B_NC(0, c+1, buf^1); CP_P_SLICE(c+1); CP_COMMIT();
        }
        COMPUTE_CHUNK(buf);
        if (c < 7) { STS_AF(buf^1, c+1); CP_WAIT0(); }
        __syncthreads();
    }

    // ---- epilogue: logit_row = sum_col relu(acc + P + b1[col]) * h[col] ----
    {
        const __half2* Ps = (const __half2*)(dsm + POFF);   // pitch 132 half2
        const int g   = lane >> 2;
        const int tg  = lane & 3;
        #pragma unroll
        for (int i = 0; i < 2; i++) {
            float p0 = 0.f, p1 = 0.f;
            int r0 = warp_m*32 + i*16 + g;
            #pragma unroll
            for (int j = 0; j < 8; j++) {
                int c0 = warp_n*64 + j*8 + tg*2;
                int c1 = c0 + 1;
                float2 pa = __half22float2(Ps[r0*132 + (c0>>1)]);
                float2 pb = __half22float2(Ps[(r0+8)*132 + (c0>>1)]);
                float h0 = hs[c0], h1 = hs[c1];
                float bb0 = b1s[c0], bb1 = b1s[c1];
                p0 += fmaxf(acc[i][j][0] + pa.x + bb0, 0.f) * h0
                    + fmaxf(acc[i][j][1] + pa.y + bb1, 0.f) * h1;
                p1 += fmaxf(acc[i][j][2] + pb.x + bb0, 0.f) * h0
                    + fmaxf(acc[i][j][3] + pb.y + bb1, 0.f) * h1;
            }
            p0 += __shfl_xor_sync(0xffffffffu, p0, 1);
            p0 += __shfl_xor_sync(0xffffffffu, p0, 2);
            p1 += __shfl_xor_sync(0xffffffffu, p1, 1);
            p1 += __shfl_xor_sync(0xffffffffu, p1, 2);
            if (tg == 0) {
                atomicAdd(&part[r0],     p0);
                atomicAdd(&part[r0 + 8], p1);
            }
        }
    }
    __syncthreads();
    if (tid < TILE_M) g_logits[tile*TILE_M + tid] = part[tid] + b2p[0];
}

// ============================================================
// Kernel C: softmax + weighted sum. 512 threads, 16 warps.
// Warp w handles rows d = w, w+16, ...: warps 0-7 do 13 rows, 8-15 do 12
// (exact trip counts, no dead guarded iterations). Lane loads the full
// 512B row via uint4. Accumulates raw e; 1/S applied once at the end.
// ============================================================
#define SACC_PITCH 264
__global__ __launch_bounds__(512)
void softmax_out_kernel(float* __restrict__ out, int write_att)
{
    __shared__ float s[DNUM];        // e values
    __shared__ float wsum[16];
    __shared__ float sinv;
    __shared__ float sacc[16*SACC_PITCH];
    int b = blockIdx.x, tid = threadIdx.x;
    int w = tid >> 5, lane = tid & 31;

    float e = 0.f;
    if (tid < DNUM) { e = expf(g_logits[b*DNUM + tid]); s[tid] = e; }
    float v = e;
    #pragma unroll
    for (int o = 16; o > 0; o >>= 1) v += __shfl_down_sync(0xffffffffu, v, o);
    if (lane == 0) wsum[w] = v;
    __syncthreads();
    if (tid == 0) {
        float S = 0.f;
        #pragma unroll
        for (int i = 0; i < 16; i++) S += wsum[i];
        sinv = 1.f / (S + 1e-8f);
    }

    // weighted sum with raw e: lane l accumulates features l*8..l*8+7
    const uint4* fb = (const uint4*)(g_feat16 + (size_t)b * DNUM * 256);
    const int nrows = (w < 8) ? 13 : 12;   // w + 16*(nrows-1) < 200
    float a0=0.f,a1=0.f,a2=0.f,a3=0.f,a4=0.f,a5=0.f,a6=0.f,a7=0.f;
    for (int t = 0; t < nrows; t++) {
        int d = w + t*16;
        float sd = s[d];
        uint4 r = fb[d*32 + lane];
        float2 f0 = __half22float2(*(__half2*)&r.x);
        float2 f1 = __half22float2(*((__half2*)&r.x + 1));
        float2 f2 = __half22float2(*(__half2*)&r.z);
        float2 f3 = __half22float2(*((__half2*)&r.z + 1));
        a0 += sd*f0.x; a1 += sd*f0.y; a2 += sd*f1.x; a3 += sd*f1.y;
        a4 += sd*f2.x; a5 += sd*f2.y; a6 += sd*f3.x; a7 += sd*f3.y;
    }
    {
        // bank-conflict-free staging: feature f stored at f + (f>>5)
        float* sa = sacc + w*SACC_PITCH;
        int f = lane*8;
        int o = f + (f >> 5);
        sa[o]   = a0; sa[o+1] = a1; sa[o+2] = a2; sa[o+3] = a3;
        sa[o+4] = a4; sa[o+5] = a5; sa[o+6] = a6; sa[o+7] = a7;
    }
    __syncthreads();
    float inv = sinv;
    if (tid < DNUM && write_att)
        out[BZ*FEATD + b*DNUM + tid] = s[tid] * inv;
    if (tid < FEATD) {
        int o = tid + (tid >> 5);
        float r = 0.f;
        #pragma unroll
        for (int ww = 0; ww < 16; ww++) r += sacc[ww*SACC_PITCH + o];
        out[b*FEATD + tid] = r * inv;
    }
}

// ============================================================
extern "C" void kernel_launch(void* const* d_in, const int* in_sizes, int n_in,
                              void* d_out, int out_size)
{
    const float* feat     = (const float*)d_in[0];
    const int*   other_id = (const int*)  d_in[1];
    const float* Wrv      = (const float*)d_in[2];
    const float* Wid      = (const float*)d_in[3];
    const float* hvec     = (const float*)d_in[4];
    const float* b1       = (const float*)d_in[5];
    const float* b2       = (const float*)d_in[6];
    const float* ebd      = (const float*)d_in[7];
    float* out = (float*)d_out;

    cudaFuncSetAttribute(precompute_p_kernel,
                         cudaFuncAttributeMaxDynamicSharedMemorySize, SMEM_PRE);
    cudaFuncSetAttribute(gemm_logits_kernel,
                         cudaFuncAttributeMaxDynamicSharedMemorySize, SMEM_TOK);

    prep_w_kernel<<<512, 256>>>(Wrv, Wid);
    precompute_p_kernel<<<PTILES, 256, SMEM_PRE>>>((const float4*)ebd);
    gemm_logits_kernel<<<NTILES, 256, SMEM_TOK>>>(
        (const float4*)feat, other_id, b1, hvec, b2);

    int write_att = (out_size >= BZ*FEATD + BZ*DNUM) ? 1 : 0;
    softmax_out_kernel<<<BZ, 512>>>(out, write_att);
}